// round 5
// baseline (speedup 1.0000x reference)
#include <cuda_runtime.h>
#include <math.h>

// Problem constants
#define B_  32
#define L_  512
#define H_  8
#define E_  64
#define S_  512

// Tiling
#define BL  32          // query rows per CTA
#define SC  128         // key/value chunk rows held in smem
#define NCH 4           // S / SC
#define NT  256         // threads per CTA

// Padded smem strides (floats)
#define KST 66          // K/V tile row stride
#define SST 516         // series row stride: %32==4 -> conflict-free LDS.128 across 8 row-groups

#define SMEM_FLOATS (BL*E_ + SC*KST + BL*SST)
#define SMEM_BYTES  (SMEM_FLOATS * 4)   // 108,032 B -> 2 CTAs/SM

// Output layout: [ V (B,L,H,E) | series (B,H,L,S) | prior (B,H,L,S) ]
#define OFF_SER ((size_t)8388608)
#define OFF_PRI ((size_t)75497472)

// Packed f32x2 FMA (Blackwell): 2 fp32 FMAs per fma-pipe issue slot.
static __device__ __forceinline__ float2 ffma2(float2 a, float2 b, float2 c) {
    float2 d;
    asm("{\n\t"
        ".reg .b64 ra, rb, rc, rd;\n\t"
        "mov.b64 ra, {%2,%3};\n\t"
        "mov.b64 rb, {%4,%5};\n\t"
        "mov.b64 rc, {%6,%7};\n\t"
        "fma.rn.f32x2 rd, ra, rb, rc;\n\t"
        "mov.b64 {%0,%1}, rd;\n\t"
        "}"
        : "=f"(d.x), "=f"(d.y)
        : "f"(a.x), "f"(a.y), "f"(b.x), "f"(b.y), "f"(c.x), "f"(c.y));
    return d;
}

__global__ void __launch_bounds__(NT, 2)
anomaly_attn_kernel(const float* __restrict__ q,
                    const float* __restrict__ kg,
                    const float* __restrict__ vg,
                    const float* __restrict__ sg,
                    float* __restrict__ out)
{
    extern __shared__ float sm[];
    float* sQ   = sm;                 // [BL][E_]
    float* sKV  = sm + BL*E_;         // [SC][KST]
    float* sSer = sKV + SC*KST;       // [BL][SST]

    const int tid  = threadIdx.x;
    const int lane = tid & 31;
    const int wid  = tid >> 5;        // 0..7
    const int tile = blockIdx.x;      // 0..15
    const int h    = blockIdx.y;
    const int b    = blockIdx.z;
    const int l0   = tile * BL;

    const float* qb = q  + (((size_t)b*L_ + l0)*H_ + h)*E_;   // row stride H_*E_
    const float* kb = kg + ((size_t)b*L_*H_ + h)*E_;          // key row s: + s*H_*E_
    const float* vb = vg + ((size_t)b*L_*H_ + h)*E_;

    // ---- Load Q tile (32x64) ----
    #pragma unroll 4
    for (int t = tid; t < BL*32; t += NT) {
        int r = t >> 5, c2 = t & 31;
        *(float2*)&sQ[r*E_ + c2*2] =
            *(const float2*)&qb[(size_t)r*(H_*E_) + c2*2];
    }

    const float scale = 0.125f;   // 1/sqrt(64)
    float rs[4] = {0.f, 0.f, 0.f, 0.f};   // row sums of exp(logits)

    // ---- QK^T + exp, chunked over S ----
    for (int ch = 0; ch < NCH; ++ch) {
        __syncthreads();
        #pragma unroll 8
        for (int t = tid; t < SC*32; t += NT) {
            int r = t >> 5, c2 = t & 31;
            *(float2*)&sKV[r*KST + c2*2] =
                *(const float2*)&kb[(size_t)(ch*SC + r)*(H_*E_) + c2*2];
        }
        __syncthreads();

        float2 acc[4][4];
        #pragma unroll
        for (int i = 0; i < 4; ++i)
            #pragma unroll
            for (int j = 0; j < 4; ++j)
                acc[i][j] = make_float2(0.f, 0.f);

        #pragma unroll 4
        for (int e2 = 0; e2 < 32; ++e2) {
            float2 a[4], bb[4];
            #pragma unroll
            for (int i = 0; i < 4; ++i)       // broadcast loads
                a[i] = *(float2*)&sQ[(wid*4 + i)*E_ + e2*2];
            #pragma unroll
            for (int j = 0; j < 4; ++j)       // spread loads (2-phase min)
                bb[j] = *(float2*)&sKV[(j*32 + lane)*KST + e2*2];
            #pragma unroll
            for (int i = 0; i < 4; ++i)
                #pragma unroll
                for (int j = 0; j < 4; ++j)
                    acc[i][j] = ffma2(a[i], bb[j], acc[i][j]);
        }

        // exp (no max-shift: |logits| small, softmax shift-invariant)
        #pragma unroll
        for (int i = 0; i < 4; ++i) {
            int r = wid*4 + i;
            #pragma unroll
            for (int j = 0; j < 4; ++j) {
                int s = ch*SC + j*32 + lane;
                float p = __expf((acc[i][j].x + acc[i][j].y) * scale);
                sSer[r*SST + s] = p;
                rs[i] += p;
            }
        }
    }

    // ---- Row-sum reduce across the warp (warp owns rows wid*4..wid*4+3) ----
    #pragma unroll
    for (int i = 0; i < 4; ++i) {
        float x = rs[i];
        #pragma unroll
        for (int off = 16; off > 0; off >>= 1)
            x += __shfl_xor_sync(0xffffffffu, x, off);
        rs[i] = 1.0f / x;
    }

    // ---- Gaussian prior per-row constants ----
    // Reproduce reference's fp32 cancellation in (3^sig - 1):
    // accurate expm1, then quantize through fl32(1+u)-1.
    float pc0[4], pc1[4];
    #pragma unroll
    for (int i = 0; i < 4; ++i) {
        int lg = l0 + wid*4 + i;
        float sv = sg[((size_t)b*L_ + lg)*H_ + h];
        float s1 = 1.0f / (1.0f + __expf(-5.0f * sv)) + 1e-5f;
        float u  = expm1f(s1 * 1.0986122886681098f);       // 3^s1 - 1, accurate
        float t3 = __fadd_rn(__fadd_rn(1.0f, u), -1.0f);   // mimic fl32(3^s1) - 1
        pc0[i] = 0.3989422804014327f / t3;
        pc1[i] = -0.5f / (t3 * t3);
    }

    // ---- Normalize series, write series + prior to gmem, finalize sSer ----
    #pragma unroll
    for (int i = 0; i < 4; ++i) {
        int r  = wid*4 + i;
        int lg = l0 + r;
        float* serrow = out + OFF_SER + (((size_t)b*H_ + h)*L_ + lg)*S_;
        float* prirow = out + OFF_PRI + (((size_t)b*H_ + h)*L_ + lg)*S_;
        #pragma unroll
        for (int jj = 0; jj < 16; ++jj) {
            int s = jj*32 + lane;
            float p = sSer[r*SST + s] * rs[i];
            sSer[r*SST + s] = p;
            serrow[s] = p;
            float d = (float)(lg - s);
            prirow[s] = pc0[i] * __expf(pc1[i] * (d * d));
        }
    }

    // ---- PV: out[32x64] = series[32x512] @ V[512x64] ----
    // Warp wid owns e-range [wid*8, wid*8+8). lane = rg*4+ep:
    // rg in 0..7 selects row group, ep in 0..3 selects e-pair.
    const int rg = lane >> 2;
    const int ep = lane & 3;
    float2 pacc[4];
    #pragma unroll
    for (int i = 0; i < 4; ++i) pacc[i] = make_float2(0.f, 0.f);

    for (int ch = 0; ch < NCH; ++ch) {
        __syncthreads();   // also guards sSer finalize before cross-warp reads
        #pragma unroll 8
        for (int t = tid; t < SC*32; t += NT) {
            int r = t >> 5, c2 = t & 31;
            *(float2*)&sKV[r*KST + c2*2] =
                *(const float2*)&vb[(size_t)(ch*SC + r)*(H_*E_) + c2*2];
        }
        __syncthreads();

        // 4-k blocking: LDS.128 on series (conflict-free, SST%32==4),
        // 8 LDS per 16 ffma2.
        #pragma unroll 2
        for (int k4 = 0; k4 < SC/4; ++k4) {
            int k0 = ch*SC + k4*4;
            float4 a4[4];
            #pragma unroll
            for (int i = 0; i < 4; ++i)
                a4[i] = *(float4*)&sSer[(size_t)(i*8 + rg)*SST + k0];
            float2 bv[4];
            #pragma unroll
            for (int kk = 0; kk < 4; ++kk)
                bv[kk] = *(float2*)&sKV[(k4*4 + kk)*KST + wid*8 + ep*2];
            #pragma unroll
            for (int i = 0; i < 4; ++i) {
                pacc[i] = ffma2(make_float2(a4[i].x, a4[i].x), bv[0], pacc[i]);
                pacc[i] = ffma2(make_float2(a4[i].y, a4[i].y), bv[1], pacc[i]);
                pacc[i] = ffma2(make_float2(a4[i].z, a4[i].z), bv[2], pacc[i]);
                pacc[i] = ffma2(make_float2(a4[i].w, a4[i].w), bv[3], pacc[i]);
            }
        }
    }

    // ---- Write V output [B,L,H,E] ----
    float* vout = out + (((size_t)b*L_ + l0)*H_ + h)*E_;
    #pragma unroll
    for (int i = 0; i < 4; ++i) {
        int r = i*8 + rg;
        *(float2*)&vout[(size_t)r*(H_*E_) + wid*8 + ep*2] = pacc[i];
    }
}

extern "C" void kernel_launch(void* const* d_in, const int* in_sizes, int n_in,
                              void* d_out, int out_size)
{
    const float* q  = (const float*)d_in[0];
    const float* k  = (const float*)d_in[1];
    const float* v  = (const float*)d_in[2];
    const float* sg = (const float*)d_in[3];
    float* out = (float*)d_out;

    cudaFuncSetAttribute(anomaly_attn_kernel,
                         cudaFuncAttributeMaxDynamicSharedMemorySize, SMEM_BYTES);

    dim3 grid(L_ / BL, H_, B_);   // (16, 8, 32)
    anomaly_attn_kernel<<<grid, NT, SMEM_BYTES>>>(q, k, v, sg, out);
}

// round 7
// speedup vs baseline: 1.0028x; 1.0028x over previous
#include <cuda_runtime.h>
#include <math.h>

// Problem constants
#define B_  32
#define L_  512
#define H_  8
#define E_  64
#define S_  512

// Tiling
#define BL  32          // query rows per CTA
#define SC  128         // key/value chunk rows held in smem
#define NCH 4           // S / SC
#define NT  256         // threads per CTA

// Padded smem strides (floats)
#define KST 66          // K/V tile row stride
#define SST 516         // series row stride: %32==4 -> conflict-free LDS.128 across 8 row-groups

#define SMEM_FLOATS (BL*E_ + SC*KST + BL*SST)
#define SMEM_BYTES  (SMEM_FLOATS * 4)   // 108,032 B -> 2 CTAs/SM

// Output layout: [ V (B,L,H,E) | series (B,H,L,S) | prior (B,H,L,S) ]
#define OFF_SER ((size_t)8388608)
#define OFF_PRI ((size_t)75497472)

// Packed f32x2 FMA (Blackwell): 2 fp32 FMAs per fma-pipe issue slot.
static __device__ __forceinline__ float2 ffma2(float2 a, float2 b, float2 c) {
    float2 d;
    asm("{\n\t"
        ".reg .b64 ra, rb, rc, rd;\n\t"
        "mov.b64 ra, {%2,%3};\n\t"
        "mov.b64 rb, {%4,%5};\n\t"
        "mov.b64 rc, {%6,%7};\n\t"
        "fma.rn.f32x2 rd, ra, rb, rc;\n\t"
        "mov.b64 {%0,%1}, rd;\n\t"
        "}"
        : "=f"(d.x), "=f"(d.y)
        : "f"(a.x), "f"(a.y), "f"(b.x), "f"(b.y), "f"(c.x), "f"(c.y));
    return d;
}

__global__ void __launch_bounds__(NT, 2)
anomaly_attn_kernel(const float* __restrict__ q,
                    const float* __restrict__ kg,
                    const float* __restrict__ vg,
                    const float* __restrict__ sg,
                    float* __restrict__ out)
{
    extern __shared__ float sm[];
    float* sQ   = sm;                 // [BL][E_]
    float* sKV  = sm + BL*E_;         // [SC][KST]
    float* sSer = sKV + SC*KST;       // [BL][SST]

    const int tid  = threadIdx.x;
    const int lane = tid & 31;
    const int wid  = tid >> 5;        // 0..7
    const int tile = blockIdx.x;      // 0..15
    const int h    = blockIdx.y;
    const int b    = blockIdx.z;
    const int l0   = tile * BL;

    const float* qb = q  + (((size_t)b*L_ + l0)*H_ + h)*E_;   // row stride H_*E_
    const float* kb = kg + ((size_t)b*L_*H_ + h)*E_;          // key row s: + s*H_*E_
    const float* vb = vg + ((size_t)b*L_*H_ + h)*E_;

    // ---- Load Q tile (32x64) ----
    #pragma unroll 4
    for (int t = tid; t < BL*32; t += NT) {
        int r = t >> 5, c2 = t & 31;
        *(float2*)&sQ[r*E_ + c2*2] =
            *(const float2*)&qb[(size_t)r*(H_*E_) + c2*2];
    }

    const float scale = 0.125f;   // 1/sqrt(64)
    float rs[4] = {0.f, 0.f, 0.f, 0.f};   // row sums of exp(logits)

    // ---- QK^T + exp, chunked over S ----
    for (int ch = 0; ch < NCH; ++ch) {
        __syncthreads();
        #pragma unroll 8
        for (int t = tid; t < SC*32; t += NT) {
            int r = t >> 5, c2 = t & 31;
            *(float2*)&sKV[r*KST + c2*2] =
                *(const float2*)&kb[(size_t)(ch*SC + r)*(H_*E_) + c2*2];
        }
        __syncthreads();

        float2 acc[4][4];
        #pragma unroll
        for (int i = 0; i < 4; ++i)
            #pragma unroll
            for (int j = 0; j < 4; ++j)
                acc[i][j] = make_float2(0.f, 0.f);

        #pragma unroll 4
        for (int e2 = 0; e2 < 32; ++e2) {
            float2 a[4], bb[4];
            #pragma unroll
            for (int i = 0; i < 4; ++i)       // broadcast loads
                a[i] = *(float2*)&sQ[(wid*4 + i)*E_ + e2*2];
            #pragma unroll
            for (int j = 0; j < 4; ++j)       // spread loads (2-phase min)
                bb[j] = *(float2*)&sKV[(j*32 + lane)*KST + e2*2];
            #pragma unroll
            for (int i = 0; i < 4; ++i)
                #pragma unroll
                for (int j = 0; j < 4; ++j)
                    acc[i][j] = ffma2(a[i], bb[j], acc[i][j]);
        }

        // exp (no max-shift: |logits| small, softmax shift-invariant)
        #pragma unroll
        for (int i = 0; i < 4; ++i) {
            int r = wid*4 + i;
            #pragma unroll
            for (int j = 0; j < 4; ++j) {
                int s = ch*SC + j*32 + lane;
                float p = __expf((acc[i][j].x + acc[i][j].y) * scale);
                sSer[r*SST + s] = p;
                rs[i] += p;
            }
        }
    }

    // ---- Row-sum reduce across the warp (warp owns rows wid*4..wid*4+3) ----
    #pragma unroll
    for (int i = 0; i < 4; ++i) {
        float x = rs[i];
        #pragma unroll
        for (int off = 16; off > 0; off >>= 1)
            x += __shfl_xor_sync(0xffffffffu, x, off);
        rs[i] = 1.0f / x;
    }

    // ---- Gaussian prior per-row constants ----
    // Reproduce reference's fp32 cancellation in (3^sig - 1):
    // accurate expm1, then quantize through fl32(1+u)-1.
    float pc0[4], pc1[4];
    #pragma unroll
    for (int i = 0; i < 4; ++i) {
        int lg = l0 + wid*4 + i;
        float sv = sg[((size_t)b*L_ + lg)*H_ + h];
        float s1 = 1.0f / (1.0f + __expf(-5.0f * sv)) + 1e-5f;
        float u  = expm1f(s1 * 1.0986122886681098f);       // 3^s1 - 1, accurate
        float t3 = __fadd_rn(__fadd_rn(1.0f, u), -1.0f);   // mimic fl32(3^s1) - 1
        pc0[i] = 0.3989422804014327f / t3;
        pc1[i] = -0.5f / (t3 * t3);
    }

    // ---- Normalize series, write series + prior to gmem, finalize sSer ----
    #pragma unroll
    for (int i = 0; i < 4; ++i) {
        int r  = wid*4 + i;
        int lg = l0 + r;
        float* serrow = out + OFF_SER + (((size_t)b*H_ + h)*L_ + lg)*S_;
        float* prirow = out + OFF_PRI + (((size_t)b*H_ + h)*L_ + lg)*S_;
        #pragma unroll
        for (int jj = 0; jj < 16; ++jj) {
            int s = jj*32 + lane;
            float p = sSer[r*SST + s] * rs[i];
            sSer[r*SST + s] = p;
            serrow[s] = p;
            float d = (float)(lg - s);
            prirow[s] = pc0[i] * __expf(pc1[i] * (d * d));
        }
    }

    // ---- PV: out[32x64] = series[32x512] @ V[512x64] ----
    // Warp wid owns e-range [wid*8, wid*8+8). lane = rg*4+ep:
    // rg in 0..7 selects row group, ep in 0..3 selects e-pair.
    const int rg = lane >> 2;
    const int ep = lane & 3;
    float2 pacc[4];
    #pragma unroll
    for (int i = 0; i < 4; ++i) pacc[i] = make_float2(0.f, 0.f);

    for (int ch = 0; ch < NCH; ++ch) {
        __syncthreads();   // also guards sSer finalize before cross-warp reads
        #pragma unroll 8
        for (int t = tid; t < SC*32; t += NT) {
            int r = t >> 5, c2 = t & 31;
            *(float2*)&sKV[r*KST + c2*2] =
                *(const float2*)&vb[(size_t)(ch*SC + r)*(H_*E_) + c2*2];
        }
        __syncthreads();

        // 4-k blocking: LDS.128 on series (conflict-free, SST%32==4),
        // 8 LDS per 16 ffma2.
        #pragma unroll 2
        for (int k4 = 0; k4 < SC/4; ++k4) {
            int k0 = ch*SC + k4*4;
            float4 a4[4];
            #pragma unroll
            for (int i = 0; i < 4; ++i)
                a4[i] = *(float4*)&sSer[(size_t)(i*8 + rg)*SST + k0];
            float2 bv[4];
            #pragma unroll
            for (int kk = 0; kk < 4; ++kk)
                bv[kk] = *(float2*)&sKV[(k4*4 + kk)*KST + wid*8 + ep*2];
            #pragma unroll
            for (int i = 0; i < 4; ++i) {
                pacc[i] = ffma2(make_float2(a4[i].x, a4[i].x), bv[0], pacc[i]);
                pacc[i] = ffma2(make_float2(a4[i].y, a4[i].y), bv[1], pacc[i]);
                pacc[i] = ffma2(make_float2(a4[i].z, a4[i].z), bv[2], pacc[i]);
                pacc[i] = ffma2(make_float2(a4[i].w, a4[i].w), bv[3], pacc[i]);
            }
        }
    }

    // ---- Write V output [B,L,H,E] ----
    float* vout = out + (((size_t)b*L_ + l0)*H_ + h)*E_;
    #pragma unroll
    for (int i = 0; i < 4; ++i) {
        int r = i*8 + rg;
        *(float2*)&vout[(size_t)r*(H_*E_) + wid*8 + ep*2] = pacc[i];
    }
}

extern "C" void kernel_launch(void* const* d_in, const int* in_sizes, int n_in,
                              void* d_out, int out_size)
{
    const float* q  = (const float*)d_in[0];
    const float* k  = (const float*)d_in[1];
    const float* v  = (const float*)d_in[2];
    const float* sg = (const float*)d_in[3];
    float* out = (float*)d_out;

    cudaFuncSetAttribute(anomaly_attn_kernel,
                         cudaFuncAttributeMaxDynamicSharedMemorySize, SMEM_BYTES);

    dim3 grid(L_ / BL, H_, B_);   // (16, 8, 32)
    anomaly_attn_kernel<<<grid, NT, SMEM_BYTES>>>(q, k, v, sg, out);
}

// round 12
// speedup vs baseline: 1.0275x; 1.0246x over previous
#include <cuda_runtime.h>
#include <cuda_bf16.h>
#include <cstdint>
#include <math.h>

// ---------------- Problem constants ----------------
#define B_  32
#define L_  512
#define H_  8
#define E_  64
#define S_  512
#define BL  32        // query rows per CTA
#define SCH 128       // key/value chunk
#define NCH 4
#define NT  128       // 4 warps: (mw = wid&1) x (nw = wid>>1)

// Output layout: [ V (B,L,H,E) | series (B,H,L,S) | prior (B,H,L,S) ]
#define OFF_SER ((size_t)8388608)
#define OFF_PRI ((size_t)75497472)

// ---------------- SMEM layout (bytes) ----------------
#define QSTR 144      // 72 bf16 per row (64 data + 8 pad) -> conflict-free ldmatrix
#define KSTR 144
#define PSTR 1040     // 520 bf16 per row (512 data + 8 pad)

#define SM_PC0   0                        // float[32] prior coef a
#define SM_PC1   128                      // float[32] prior coef b
#define SM_RS    256                      // float[64] rowsum partials (2 n-warps x 32 rows)
#define SM_RINV  512                      // float[32]
#define SM_QHI   1024
#define SM_QLO   (SM_QHI + 32*QSTR)       // 5632
#define SM_KHI   (SM_QLO + 32*QSTR)       // 10240  (K, later V, chunk: 128 rows)
#define SM_KLO   (SM_KHI + 128*KSTR)      // 28672
#define SM_PHI   (SM_KLO + 128*KSTR)      // 47104  (P~ tile: 32 x 512 bf16)
#define SM_PLO   (SM_PHI + 32*PSTR)       // 80384
#define SMEM_TOTAL (SM_PLO + 32*PSTR)     // 113664 -> 2 CTAs/SM

// ---------------- Tensor-op helpers (baseline PTX, sm_80+) ----------------
#define MMA16816(d, a, b0, b1) \
    asm volatile("mma.sync.aligned.m16n8k16.row.col.f32.bf16.bf16.f32 " \
                 "{%0,%1,%2,%3}, {%4,%5,%6,%7}, {%8,%9}, {%0,%1,%2,%3};" \
                 : "+f"((d)[0]), "+f"((d)[1]), "+f"((d)[2]), "+f"((d)[3]) \
                 : "r"((a)[0]), "r"((a)[1]), "r"((a)[2]), "r"((a)[3]), "r"(b0), "r"(b1))

#define LDSM4(r, a) \
    asm volatile("ldmatrix.sync.aligned.m8n8.x4.shared.b16 {%0,%1,%2,%3}, [%4];" \
                 : "=r"((r)[0]), "=r"((r)[1]), "=r"((r)[2]), "=r"((r)[3]) : "r"(a))
#define LDSM2(r0, r1, a) \
    asm volatile("ldmatrix.sync.aligned.m8n8.x2.shared.b16 {%0,%1}, [%2];" \
                 : "=r"(r0), "=r"(r1) : "r"(a))
#define LDSM2T(r0, r1, a) \
    asm volatile("ldmatrix.sync.aligned.m8n8.x2.trans.shared.b16 {%0,%1}, [%2];" \
                 : "=r"(r0), "=r"(r1) : "r"(a))

static __device__ __forceinline__ uint32_t smem_u32(const void* p) {
    uint32_t a;
    asm("{ .reg .u64 t; cvta.to.shared.u64 t, %1; cvt.u32.u64 %0, t; }" : "=r"(a) : "l"(p));
    return a;
}

// ---------------- bf16 hi/lo split helpers ----------------
static __device__ __forceinline__ void split2(float a, float b, uint32_t& hi, uint32_t& lo) {
    __nv_bfloat16 ha = __float2bfloat16(a), hb = __float2bfloat16(b);
    hi = (uint32_t)__bfloat16_as_ushort(ha) | ((uint32_t)__bfloat16_as_ushort(hb) << 16);
    __nv_bfloat16 la = __float2bfloat16(a - __bfloat162float(ha));
    __nv_bfloat16 lb = __float2bfloat16(b - __bfloat162float(hb));
    lo = (uint32_t)__bfloat16_as_ushort(la) | ((uint32_t)__bfloat16_as_ushort(lb) << 16);
}
static __device__ __forceinline__ void split4(float4 v, uint2& hi, uint2& lo) {
    split2(v.x, v.y, hi.x, lo.x);
    split2(v.z, v.w, hi.y, lo.y);
}
static __device__ __forceinline__ float2 unpk(uint32_t w) {
    return make_float2(
        __bfloat162float(__ushort_as_bfloat16((unsigned short)(w & 0xffffu))),
        __bfloat162float(__ushort_as_bfloat16((unsigned short)(w >> 16))));
}

// Convert one 128x64 fp32 K/V chunk row (row = tid) into bf16 hi/lo smem tiles.
static __device__ __forceinline__ void load_conv_kv(const float* rowbase, char* smc, int tid) {
    const float4* s4 = (const float4*)rowbase;
    char* hp = smc + SM_KHI + tid * KSTR;
    char* lp = smc + SM_KLO + tid * KSTR;
    #pragma unroll
    for (int g = 0; g < 16; ++g) {
        uint2 hi, lo; split4(s4[g], hi, lo);
        *(uint2*)(hp + g*8) = hi;
        *(uint2*)(lp + g*8) = lo;
    }
}

__global__ void __launch_bounds__(NT, 2)
anomaly_attn_hmma(const float* __restrict__ q,
                  const float* __restrict__ kg,
                  const float* __restrict__ vg,
                  const float* __restrict__ sg,
                  float* __restrict__ out)
{
    extern __shared__ char smc[];
    const uint32_t sb = smem_u32(smc);
    float* spc0 = (float*)(smc + SM_PC0);
    float* spc1 = (float*)(smc + SM_PC1);
    float* sRS  = (float*)(smc + SM_RS);
    float* sRI  = (float*)(smc + SM_RINV);

    const int tid  = threadIdx.x;
    const int lane = tid & 31;
    const int wid  = tid >> 5;
    const int mw   = wid & 1;          // m-half: rows mw*16
    const int nw   = wid >> 1;         // n-half
    const int m0   = mw * 16;
    const int h    = blockIdx.y;
    const int b    = blockIdx.z;
    const int l0   = blockIdx.x * BL;

    const float* qb = q  + (((size_t)b*L_ + l0)*H_ + h)*E_;
    const float* kb = kg + ((size_t)b*L_*H_ + h)*E_;
    const float* vb = vg + ((size_t)b*L_*H_ + h)*E_;

    // Prior per-row constants (reference's fp32 cancellation reproduced)
    if (tid < 32) {
        float sv = sg[((size_t)b*L_ + l0 + tid)*H_ + h];
        float s1 = 1.0f / (1.0f + __expf(-5.0f * sv)) + 1e-5f;
        float u  = expm1f(s1 * 1.0986122886681098f);
        float t3 = __fadd_rn(__fadd_rn(1.0f, u), -1.0f);
        spc0[tid] = 0.3989422804014327f / t3;
        spc1[tid] = -0.5f / (t3 * t3);
    }

    // Q convert: row = tid>>2, quarter = tid&3 (16 cols each)
    {
        int r = tid >> 2, qr = tid & 3;
        const float4* s4 = (const float4*)(qb + (size_t)r*(H_*E_) + qr*16);
        char* hp = smc + SM_QHI + r*QSTR + qr*32;
        char* lp = smc + SM_QLO + r*QSTR + qr*32;
        #pragma unroll
        for (int g = 0; g < 4; ++g) {
            uint2 hi, lo; split4(s4[g], hi, lo);
            *(uint2*)(hp + g*8) = hi;
            *(uint2*)(lp + g*8) = lo;
        }
    }
    // K chunk 0
    load_conv_kv(kb + (size_t)tid*(H_*E_), smc, tid);
    __syncthreads();

    // Q A-fragments (persist across all chunks): [kt][4] hi and lo
    uint32_t aHq[4][4], aLq[4][4];
    {
        uint32_t rowb = (uint32_t)((m0 + (lane & 15)) * QSTR);
        uint32_t colb = (uint32_t)((lane >> 4) * 16);   // (l>>4)*8 cols * 2B
        #pragma unroll
        for (int kt = 0; kt < 4; ++kt) {
            uint32_t a = sb + SM_QHI + rowb + colb + (uint32_t)(kt*32);
            LDSM4(aHq[kt], a);
            LDSM4(aLq[kt], a + (SM_QLO - SM_QHI));
        }
    }

    float rs0 = 0.f, rs1 = 0.f;      // rowsum partials for rows r0, r0+8

    // ================= QK phase =================
    for (int ch = 0; ch < NCH; ++ch) {
        float acc[8][4];
        #pragma unroll
        for (int i = 0; i < 8; ++i)
            #pragma unroll
            for (int j = 0; j < 4; ++j) acc[i][j] = 0.f;

        // B addr base: row = nw*64 + nt*8 + (l&7); col = kt*16 + ((l>>3)&1)*8
        uint32_t brow = (uint32_t)((nw*64 + (lane & 7)) * KSTR);
        uint32_t bcol = (uint32_t)(((lane >> 3) & 1) * 16);
        #pragma unroll
        for (int nt = 0; nt < 8; ++nt) {
            #pragma unroll
            for (int kt = 0; kt < 4; ++kt) {
                uint32_t a = sb + SM_KHI + brow + (uint32_t)(nt*8*KSTR) + bcol + (uint32_t)(kt*32);
                uint32_t bh0, bh1, bl0, bl1;
                LDSM2(bh0, bh1, a);
                LDSM2(bl0, bl1, a + (SM_KLO - SM_KHI));
                MMA16816(acc[nt], aHq[kt], bh0, bh1);
                MMA16816(acc[nt], aHq[kt], bl0, bl1);
                MMA16816(acc[nt], aLq[kt], bh0, bh1);
            }
            // epilogue: exp, rowsum, store unnormalized P~ (bf16 hi/lo)
            float p0 = __expf(acc[nt][0] * 0.125f);
            float p1 = __expf(acc[nt][1] * 0.125f);
            float p2 = __expf(acc[nt][2] * 0.125f);
            float p3 = __expf(acc[nt][3] * 0.125f);
            rs0 += p0 + p1;  rs1 += p2 + p3;
            uint32_t h01, l01, h23, l23;
            split2(p0, p1, h01, l01);
            split2(p2, p3, h23, l23);
            int rowp = m0 + (lane >> 2);
            int colb2 = (ch*128 + nw*64 + nt*8 + 2*(lane & 3)) * 2;
            *(uint32_t*)(smc + SM_PHI + rowp*PSTR + colb2)       = h01;
            *(uint32_t*)(smc + SM_PLO + rowp*PSTR + colb2)       = l01;
            *(uint32_t*)(smc + SM_PHI + (rowp+8)*PSTR + colb2)   = h23;
            *(uint32_t*)(smc + SM_PLO + (rowp+8)*PSTR + colb2)   = l23;
        }

        if (ch == NCH-1) {
            // quad reduce (lanes sharing a row differ only in lane&3)
            rs0 += __shfl_xor_sync(0xffffffffu, rs0, 1);
            rs0 += __shfl_xor_sync(0xffffffffu, rs0, 2);
            rs1 += __shfl_xor_sync(0xffffffffu, rs1, 1);
            rs1 += __shfl_xor_sync(0xffffffffu, rs1, 2);
            if ((lane & 3) == 0) {
                int r0 = m0 + (lane >> 2);
                sRS[nw*32 + r0]     = rs0;
                sRS[nw*32 + r0 + 8] = rs1;
            }
        }
        __syncthreads();
        if (ch < NCH-1) load_conv_kv(kb + (size_t)((ch+1)*SCH + tid)*(H_*E_), smc, tid);
        else            load_conv_kv(vb + (size_t)tid*(H_*E_), smc, tid);   // V chunk 0
        if (ch == NCH-1 && tid < 32) sRI[tid] = 1.0f / (sRS[tid] + sRS[32 + tid]);
        __syncthreads();
    }

    // ================= PV phase (+ series/prior writes) =================
    float accPV[4][4];
    #pragma unroll
    for (int i = 0; i < 4; ++i)
        #pragma unroll
        for (int j = 0; j < 4; ++j) accPV[i][j] = 0.f;

    float* serrow0 = out + OFF_SER + (((size_t)b*H_ + h)*L_ + l0)*S_;
    float* prirow0 = out + OFF_PRI + (((size_t)b*H_ + h)*L_ + l0)*S_;

    for (int ch = 0; ch < NCH; ++ch) {
        // A (P~) addr base: row = m0+(l&15); col = ch*128 + kt*16 + (l>>4)*8
        uint32_t parow = (uint32_t)((m0 + (lane & 15)) * PSTR);
        uint32_t pacol = (uint32_t)(ch*256 + (lane >> 4) * 16);
        // B (V) trans addr: row = kt*16 + (l&15); col = nw*32 + nt*8
        uint32_t vrow = (uint32_t)((lane & 15) * KSTR);
        uint32_t vcol = (uint32_t)(nw * 64);                    // nw*32 cols * 2B
        #pragma unroll
        for (int kt = 0; kt < 8; ++kt) {
            uint32_t aaddr = sb + SM_PHI + parow + pacol + (uint32_t)(kt*32);
            uint32_t aH[4], aL[4];
            LDSM4(aH, aaddr);
            LDSM4(aL, aaddr + (SM_PLO - SM_PHI));
            #pragma unroll
            for (int nt = 0; nt < 4; ++nt) {
                uint32_t baddr = sb + SM_KHI + vrow + (uint32_t)(kt*16*KSTR) + vcol + (uint32_t)(nt*16);
                uint32_t bh0, bh1, bl0, bl1;
                LDSM2T(bh0, bh1, baddr);
                LDSM2T(bl0, bl1, baddr + (SM_KLO - SM_KHI));
                MMA16816(accPV[nt], aH, bh0, bh1);
                MMA16816(accPV[nt], aH, bl0, bl1);
                MMA16816(accPV[nt], aL, bh0, bh1);
            }
        }

        // series + prior coalesced writes for this chunk (overlap with MMA drain)
        #pragma unroll
        for (int it = 0; it < 8; ++it) {
            int idx = tid + it*NT;           // 0..1023
            int row = idx >> 5, q4 = idx & 31;
            int colg = ch*128 + q4*4;
            uint2 hi2 = *(uint2*)(smc + SM_PHI + row*PSTR + colg*2);
            uint2 lo2 = *(uint2*)(smc + SM_PLO + row*PSTR + colg*2);
            float ri = sRI[row];
            float2 u0 = unpk(hi2.x), v0 = unpk(lo2.x);
            float2 u1 = unpk(hi2.y), v1 = unpk(lo2.y);
            float4 sv;
            sv.x = (u0.x + v0.x) * ri;  sv.y = (u0.y + v0.y) * ri;
            sv.z = (u1.x + v1.x) * ri;  sv.w = (u1.y + v1.y) * ri;
            *(float4*)(serrow0 + (size_t)row*S_ + colg) = sv;
            float a0 = spc1[row], a1 = spc0[row];
            float d0 = (float)(l0 + row - colg);
            float4 pr;
            pr.x = a1 * __expf(a0 * d0 * d0);
            float d1 = d0 - 1.0f; pr.y = a1 * __expf(a0 * d1 * d1);
            float d2 = d0 - 2.0f; pr.z = a1 * __expf(a0 * d2 * d2);
            float d3 = d0 - 3.0f; pr.w = a1 * __expf(a0 * d3 * d3);
            *(float4*)(prirow0 + (size_t)row*S_ + colg) = pr;
        }

        __syncthreads();
        if (ch < NCH-1) {
            load_conv_kv(vb + (size_t)((ch+1)*SCH + tid)*(H_*E_), smc, tid);
            __syncthreads();
        }
    }

    // ================= V output =================
    {
        int r0 = m0 + (lane >> 2), r1 = r0 + 8;
        float ri0 = sRI[r0], ri1 = sRI[r1];
        float* v0p = out + (((size_t)b*L_ + l0 + r0)*H_ + h)*E_;
        float* v1p = out + (((size_t)b*L_ + l0 + r1)*H_ + h)*E_;
        #pragma unroll
        for (int nt = 0; nt < 4; ++nt) {
            int n = nw*32 + nt*8 + 2*(lane & 3);
            *(float2*)(v0p + n) = make_float2(accPV[nt][0]*ri0, accPV[nt][1]*ri0);
            *(float2*)(v1p + n) = make_float2(accPV[nt][2]*ri1, accPV[nt][3]*ri1);
        }
    }
}

extern "C" void kernel_launch(void* const* d_in, const int* in_sizes, int n_in,
                              void* d_out, int out_size)
{
    const float* q  = (const float*)d_in[0];
    const float* k  = (const float*)d_in[1];
    const float* v  = (const float*)d_in[2];
    const float* sg = (const float*)d_in[3];
    float* out = (float*)d_out;

    cudaFuncSetAttribute(anomaly_attn_hmma,
                         cudaFuncAttributeMaxDynamicSharedMemorySize, SMEM_TOTAL);

    dim3 grid(L_ / BL, H_, B_);   // (16, 8, 32)
    anomaly_attn_hmma<<<grid, NT, SMEM_TOTAL>>>(q, k, v, sg, out);
}